// round 8
// baseline (speedup 1.0000x reference)
#include <cuda_runtime.h>
#include <cuda_bf16.h>
#include <cstdint>

// Problem constants: N=512, A=1024, B=64, C=16
#define NN   512
#define AA   1024
#define BB   64
#define CC   16
#define OUTW (AA + BB)   // 1088

#define NGRP   16            // row groups of 32
#define GSZ    32
#define NTILES (NGRP * (NGRP + 1) / 2)   // 136

#define LOG2E 1.44269504088896340736f

// ---------------- device scratch ----------------
// M (pre-scaled by log2e) in bf16x2: g_Mb[row*512 + b*8 + c2]
__device__ uint32_t g_Mb[NN * 512];
// partial sums: g_Pp[src_group][row][b]; every slot written exactly once
__device__ float g_Pp[NGRP][NN * BB];
__device__ __nv_bfloat16 g_xb[NN * AA];     // x in bf16
__device__ __nv_bfloat16 g_Wb[AA * AA];     // W^T * log2e in bf16: g_Wb[n][k]

// ---------------- helpers ----------------
__device__ __forceinline__ uint32_t smem_u32(const void* p) {
    uint32_t a;
    asm("{ .reg .u64 t; cvta.to.shared.u64 t, %1; cvt.u32.u64 %0, t; }" : "=r"(a) : "l"(p));
    return a;
}
#define LDMATRIX_X4(r0, r1, r2, r3, addr) \
    asm volatile("ldmatrix.sync.aligned.m8n8.x4.shared.b16 {%0,%1,%2,%3}, [%4];" \
        : "=r"(r0), "=r"(r1), "=r"(r2), "=r"(r3) : "r"(addr))

__device__ __forceinline__ void mma_bf16(float d[4], const uint32_t a[4], const uint32_t b[2]) {
    asm volatile(
        "mma.sync.aligned.m16n8k16.row.col.f32.bf16.bf16.f32 "
        "{%0,%1,%2,%3}, {%4,%5,%6,%7}, {%8,%9}, {%0,%1,%2,%3};"
        : "+f"(d[0]), "+f"(d[1]), "+f"(d[2]), "+f"(d[3])
        : "r"(a[0]), "r"(a[1]), "r"(a[2]), "r"(a[3]), "r"(b[0]), "r"(b[1]));
}

__device__ __forceinline__ __nv_bfloat162 u2b(uint32_t u) {
    return *reinterpret_cast<__nv_bfloat162*>(&u);
}
__device__ __forceinline__ uint32_t b2u(__nv_bfloat162 v) {
    return *reinterpret_cast<uint32_t*>(&v);
}
__device__ __forceinline__ float ex2(float v) {
    float r; asm("ex2.approx.f32 %0, %1;" : "=f"(r) : "f"(v)); return r;
}

// -(L1 over 16 bf16 components held as 8 bf16x2 regs); exact lo/hi extraction.
__device__ __forceinline__ float l1_neg(const uint32_t* mj, const uint32_t* mi) {
    __nv_bfloat162 d0 = __habs2(__hsub2(u2b(mj[0]), u2b(mi[0])));
    __nv_bfloat162 d1 = __habs2(__hsub2(u2b(mj[1]), u2b(mi[1])));
    __nv_bfloat162 d2 = __habs2(__hsub2(u2b(mj[2]), u2b(mi[2])));
    __nv_bfloat162 d3 = __habs2(__hsub2(u2b(mj[3]), u2b(mi[3])));
    __nv_bfloat162 d4 = __habs2(__hsub2(u2b(mj[4]), u2b(mi[4])));
    __nv_bfloat162 d5 = __habs2(__hsub2(u2b(mj[5]), u2b(mi[5])));
    __nv_bfloat162 d6 = __habs2(__hsub2(u2b(mj[6]), u2b(mi[6])));
    __nv_bfloat162 d7 = __habs2(__hsub2(u2b(mj[7]), u2b(mi[7])));
    __nv_bfloat162 s = __hadd2(__hadd2(__hadd2(d0, d1), __hadd2(d2, d3)),
                               __hadd2(__hadd2(d4, d5), __hadd2(d6, d7)));
    uint32_t u = b2u(s);
    float lo = __uint_as_float(u << 16);          // bf16 -> f32 zero-extension: exact
    float hi = __uint_as_float(u & 0xFFFF0000u);
    return (-lo) - hi;                            // FADD with neg modifiers
}

// ---------------------------------------------------------------------------
// Fused prep: blocks [0,256): copy x -> out and convert x -> g_xb (bf16).
//             blocks [256,1280): transpose+scale W -> g_Wb (bf16).
// ---------------------------------------------------------------------------
__global__ __launch_bounds__(256)
void prep_kernel(const float* __restrict__ x, const float* __restrict__ W,
                 float* __restrict__ out) {
    if (blockIdx.x < 256) {
        int t = blockIdx.x * 256 + threadIdx.x;     // handles 8 floats
        int row  = t >> 7;
        int col8 = (t & 127) * 8;
        const float4* src = reinterpret_cast<const float4*>(x + (size_t)row * AA + col8);
        float4 a = src[0], b = src[1];
        // copy to out
        float4* dst = reinterpret_cast<float4*>(out + (size_t)row * OUTW + col8);
        dst[0] = a; dst[1] = b;
        // convert to bf16
        __nv_bfloat162 p0 = __float22bfloat162_rn(make_float2(a.x, a.y));
        __nv_bfloat162 p1 = __float22bfloat162_rn(make_float2(a.z, a.w));
        __nv_bfloat162 p2 = __float22bfloat162_rn(make_float2(b.x, b.y));
        __nv_bfloat162 p3 = __float22bfloat162_rn(make_float2(b.z, b.w));
        uint4 o; o.x = b2u(p0); o.y = b2u(p1); o.z = b2u(p2); o.w = b2u(p3);
        reinterpret_cast<uint4*>(g_xb)[t] = o;
    } else {
        __shared__ float tile[32][33];
        int idx = blockIdx.x - 256;                 // 0..1023
        const int n0 = (idx & 31) * 32;
        const int k0 = (idx >> 5) * 32;
        const int tx = threadIdx.x & 31;
        const int ty = threadIdx.x >> 5;            // 0..7
#pragma unroll
        for (int r = 0; r < 4; r++)
            tile[ty + 8 * r][tx] = W[(size_t)(k0 + ty + 8 * r) * AA + n0 + tx];
        __syncthreads();
#pragma unroll
        for (int r = 0; r < 4; r++) {
            int n = n0 + ty + 8 * r;
            g_Wb[(size_t)n * AA + k0 + tx] =
                __float2bfloat16(tile[tx][ty + 8 * r] * LOG2E);
        }
    }
}

// ---------------------------------------------------------------------------
// GEMM via mma.sync bf16 m16n8k16. Block 64x64, 128 threads (4 warps 2x2),
// K chunked by 64, swizzled smem, register prefetch. Epilogue -> bf16 g_Mb.
// ---------------------------------------------------------------------------
#define BK 64
#define NCH (AA / BK)   // 16

__global__ __launch_bounds__(128)
void gemm_mma_kernel() {
    __shared__ __align__(1024) __nv_bfloat16 sA[64 * BK];   // 8 KB
    __shared__ __align__(1024) __nv_bfloat16 sB[64 * BK];   // 8 KB

    const int tid = threadIdx.x;
    const int wid = tid >> 5;
    const int l   = tid & 31;
    const int mw  = wid & 1;
    const int nw  = wid >> 1;
    const int row0 = blockIdx.y * 64;
    const int col0 = blockIdx.x * 64;

    const uint32_t sA_addr = smem_u32(sA);
    const uint32_t sB_addr = smem_u32(sB);

    float acc[2][4][4];
#pragma unroll
    for (int mt = 0; mt < 2; mt++)
#pragma unroll
        for (int nt = 0; nt < 4; nt++)
#pragma unroll
            for (int e = 0; e < 4; e++) acc[mt][nt][e] = 0.0f;

    uint4 pa[4], pb[4];
#pragma unroll
    for (int s = 0; s < 4; s++) {
        int ch = tid + s * 128;
        int r = ch >> 3, u = ch & 7;
        pa[s] = *reinterpret_cast<const uint4*>(g_xb + (size_t)(row0 + r) * AA + u * 8);
        pb[s] = *reinterpret_cast<const uint4*>(g_Wb + (size_t)(col0 + r) * AA + u * 8);
    }

    const int aRow0 = ((l >> 3) & 1) * 8 + (l & 7) + mw * 32;
    const int bRow0 = nw * 32 + ((l >> 4) << 3) + (l & 7);
    const int aKsel = (l >> 4);
    const int bKsel = ((l >> 3) & 1);
    const int swz   = (l & 7);

    for (int c = 0; c < NCH; c++) {
#pragma unroll
        for (int s = 0; s < 4; s++) {
            int ch = tid + s * 128;
            int r = ch >> 3, u = ch & 7;
            uint32_t off = (uint32_t)(r * 128 + ((u ^ (r & 7)) << 4));
            *reinterpret_cast<uint4*>(reinterpret_cast<char*>(sA) + off) = pa[s];
            *reinterpret_cast<uint4*>(reinterpret_cast<char*>(sB) + off) = pb[s];
        }
        __syncthreads();

        if (c + 1 < NCH) {
            int k0 = (c + 1) * BK;
#pragma unroll
            for (int s = 0; s < 4; s++) {
                int ch = tid + s * 128;
                int r = ch >> 3, u = ch & 7;
                pa[s] = *reinterpret_cast<const uint4*>(g_xb + (size_t)(row0 + r) * AA + k0 + u * 8);
                pb[s] = *reinterpret_cast<const uint4*>(g_Wb + (size_t)(col0 + r) * AA + k0 + u * 8);
            }
        }

#pragma unroll
        for (int ks = 0; ks < 4; ks++) {
            uint32_t af[2][4], bf[4][2];
#pragma unroll
            for (int mt = 0; mt < 2; mt++) {
                int row = aRow0 + mt * 16;
                uint32_t u = (uint32_t)(ks * 2 + aKsel);
                uint32_t addr = sA_addr + (uint32_t)(row * 128) + (((u ^ swz)) << 4);
                LDMATRIX_X4(af[mt][0], af[mt][1], af[mt][2], af[mt][3], addr);
            }
#pragma unroll
            for (int ng = 0; ng < 2; ng++) {
                int row = bRow0 + ng * 16;
                uint32_t u = (uint32_t)(ks * 2 + bKsel);
                uint32_t addr = sB_addr + (uint32_t)(row * 128) + (((u ^ swz)) << 4);
                uint32_t r0, r1, r2, r3;
                LDMATRIX_X4(r0, r1, r2, r3, addr);
                bf[ng * 2 + 0][0] = r0; bf[ng * 2 + 0][1] = r1;
                bf[ng * 2 + 1][0] = r2; bf[ng * 2 + 1][1] = r3;
            }
#pragma unroll
            for (int mt = 0; mt < 2; mt++)
#pragma unroll
                for (int nt = 0; nt < 4; nt++)
                    mma_bf16(acc[mt][nt], af[mt], bf[nt]);
        }
        __syncthreads();
    }

    // Epilogue: bf16x2 into pairwise layout g_Mb[row*512 + b*8 + c2]
    const int g = l >> 2;
    const int cc2 = (l & 3) * 2;
#pragma unroll
    for (int mt = 0; mt < 2; mt++) {
#pragma unroll
        for (int nt = 0; nt < 4; nt++) {
            int gcol = col0 + nw * 32 + nt * 8 + cc2;
            int b  = gcol >> 4;
            int c2 = (gcol & 15) >> 1;
            int rowA = row0 + mw * 32 + mt * 16 + g;
            __nv_bfloat162 v0 = __float22bfloat162_rn(
                make_float2(acc[mt][nt][0], acc[mt][nt][1]));
            __nv_bfloat162 v1 = __float22bfloat162_rn(
                make_float2(acc[mt][nt][2], acc[mt][nt][3]));
            g_Mb[(size_t)rowA * 512 + b * 8 + c2]       = b2u(v0);
            g_Mb[(size_t)(rowA + 8) * 512 + b * 8 + c2] = b2u(v1);
        }
    }
}

// ---------------------------------------------------------------------------
// Pairwise, triangular tiles over 16 groups of 32 rows. 136 blocks x 512 thr
// (single co-resident wave). Thread (b = t&63, isp = t>>6 in 0..7): owns
// 4 i-rows, loops 32 j-rows (prefetch depth 2). j-side reduced in two
// 16-row halves against a 32 KB smem buffer.
// ---------------------------------------------------------------------------
__global__ __launch_bounds__(512)
void pairwise_kernel() {
    const int t   = threadIdx.x;
    const int b   = t & 63;
    const int isp = t >> 6;        // 0..7

    // decode triangular tile: offset(g) = g*(33-g)/2 for NGRP=16
    int tt = blockIdx.x;
    int gi = 0;
#pragma unroll
    for (int g = 1; g < NGRP; g++)
        if ((g * (2 * NGRP + 1 - g)) / 2 <= tt) gi = g;
    int gj = gi + (tt - (gi * (2 * NGRP + 1 - gi)) / 2);

    const int i0 = gi * GSZ + isp * 4;
    const int j0 = gj * GSZ;

    __shared__ float red[16][8][BB];   // 32 KB (half of the j-group at a time)

    const uint4* Mb4 = reinterpret_cast<const uint4*>(g_Mb);

    // load 4 i-rows (8 u32 each)
    uint32_t mi[4][8];
#pragma unroll
    for (int k = 0; k < 4; k++) {
        uint4 v0 = Mb4[(size_t)(i0 + k) * 128 + b * 2];
        uint4 v1 = Mb4[(size_t)(i0 + k) * 128 + b * 2 + 1];
        mi[k][0] = v0.x; mi[k][1] = v0.y; mi[k][2] = v0.z; mi[k][3] = v0.w;
        mi[k][4] = v1.x; mi[k][5] = v1.y; mi[k][6] = v1.z; mi[k][7] = v1.w;
    }

    float acc_i[4] = {0.f, 0.f, 0.f, 0.f};

    // prefetch depth 2 on j-rows
    uint32_t jb[2][8];
#pragma unroll
    for (int p = 0; p < 2; p++) {
        uint4 v0 = Mb4[(size_t)(j0 + p) * 128 + b * 2];
        uint4 v1 = Mb4[(size_t)(j0 + p) * 128 + b * 2 + 1];
        jb[p][0] = v0.x; jb[p][1] = v0.y; jb[p][2] = v0.z; jb[p][3] = v0.w;
        jb[p][4] = v1.x; jb[p][5] = v1.y; jb[p][6] = v1.z; jb[p][7] = v1.w;
    }

    for (int half = 0; half < 2; half++) {
#pragma unroll
        for (int jj = 0; jj < 16; jj++) {
            const int jg = half * 16 + jj;
            uint32_t mj[8];
#pragma unroll
            for (int c = 0; c < 8; c++) mj[c] = jb[jg & 1][c];
            if (jg + 2 < GSZ) {
                uint4 v0 = Mb4[(size_t)(j0 + jg + 2) * 128 + b * 2];
                uint4 v1 = Mb4[(size_t)(j0 + jg + 2) * 128 + b * 2 + 1];
                jb[jg & 1][0] = v0.x; jb[jg & 1][1] = v0.y;
                jb[jg & 1][2] = v0.z; jb[jg & 1][3] = v0.w;
                jb[jg & 1][4] = v1.x; jb[jg & 1][5] = v1.y;
                jb[jg & 1][6] = v1.z; jb[jg & 1][7] = v1.w;
            }

            float e0 = ex2(l1_neg(mj, mi[0]));
            float e1 = ex2(l1_neg(mj, mi[1]));
            float e2 = ex2(l1_neg(mj, mi[2]));
            float e3 = ex2(l1_neg(mj, mi[3]));
            acc_i[0] += e0; acc_i[1] += e1; acc_i[2] += e2; acc_i[3] += e3;
            red[jj][isp][b] = (e0 + e1) + (e2 + e3);
        }
        __syncthreads();
        // j-side flush for this half (off-diagonal tiles only; src = gi)
        if (gi != gj) {
#pragma unroll
            for (int w = 0; w < 2; w++) {
                int cell = t + w * 512;           // 0..1023
                int jj = cell >> 6;
                int bb = cell & 63;
                float s = red[jj][0][bb] + red[jj][1][bb] + red[jj][2][bb] + red[jj][3][bb]
                        + red[jj][4][bb] + red[jj][5][bb] + red[jj][6][bb] + red[jj][7][bb];
                g_Pp[gi][(size_t)(j0 + half * 16 + jj) * BB + bb] = s;
            }
        }
        __syncthreads();
    }

    // i-side: unique slot per thread (src = gj)
#pragma unroll
    for (int k = 0; k < 4; k++)
        g_Pp[gj][(size_t)(i0 + k) * BB + b] = acc_i[k];
}

// ---------------------------------------------------------------------------
// Combine: out[i, 1024+b] = sum over 16 src planes - 1. One thread per
// output, 16 independent loads into 4 accumulators (MLP 16).
// grid 128 x 256 threads.
// ---------------------------------------------------------------------------
__global__ __launch_bounds__(256)
void combine_kernel(float* __restrict__ out) {
    const int idx = blockIdx.x * 256 + threadIdx.x;   // 0..32767
    const int i = idx >> 6;
    const int b = idx & 63;
    const size_t o = (size_t)i * BB + b;

    float s0 = 0.f, s1 = 0.f, s2 = 0.f, s3 = 0.f;
#pragma unroll
    for (int k = 0; k < 4; k++) {
        s0 += g_Pp[k][o];
        s1 += g_Pp[4 + k][o];
        s2 += g_Pp[8 + k][o];
        s3 += g_Pp[12 + k][o];
    }
    out[(size_t)i * OUTW + AA + b] = ((s0 + s1) + (s2 + s3)) - 1.0f;
}

// ---------------------------------------------------------------------------
extern "C" void kernel_launch(void* const* d_in, const int* in_sizes, int n_in,
                              void* d_out, int out_size) {
    const float* x = (const float*)d_in[0];   // (512, 1024)
    const float* T = (const float*)d_in[1];   // (1024, 1024)
    float* out = (float*)d_out;               // (512, 1088)

    prep_kernel<<<1280, 256>>>(x, T, out);

    dim3 ggrid(AA / 64, NN / 64);             // (16, 8) = 128 blocks
    gemm_mma_kernel<<<ggrid, 128>>>();

    pairwise_kernel<<<NTILES, 512>>>();       // 136 blocks, single wave

    combine_kernel<<<128, 256>>>(out);
}

// round 9
// speedup vs baseline: 1.0602x; 1.0602x over previous
#include <cuda_runtime.h>
#include <cuda_bf16.h>
#include <cstdint>

// Problem constants: N=512, A=1024, B=64, C=16
#define NN   512
#define AA   1024
#define BB   64
#define CC   16
#define OUTW (AA + BB)   // 1088

#define NGRP   16            // row groups of 32
#define GSZ    32
#define NTILES (NGRP * (NGRP + 1) / 2)   // 136

#define LOG2E 1.44269504088896340736f

// ---------------- device scratch ----------------
// M (pre-scaled by log2e) in bf16x2: g_Mb[row*512 + b*8 + c2]
__device__ uint32_t g_Mb[NN * 512];
__device__ __nv_bfloat16 g_xb[NN * AA];     // x in bf16
__device__ __nv_bfloat16 g_Wb[AA * AA];     // W^T * log2e in bf16: g_Wb[n][k]

// ---------------- helpers ----------------
__device__ __forceinline__ uint32_t smem_u32(const void* p) {
    uint32_t a;
    asm("{ .reg .u64 t; cvta.to.shared.u64 t, %1; cvt.u32.u64 %0, t; }" : "=r"(a) : "l"(p));
    return a;
}
#define LDMATRIX_X4(r0, r1, r2, r3, addr) \
    asm volatile("ldmatrix.sync.aligned.m8n8.x4.shared.b16 {%0,%1,%2,%3}, [%4];" \
        : "=r"(r0), "=r"(r1), "=r"(r2), "=r"(r3) : "r"(addr))

__device__ __forceinline__ void mma_bf16(float d[4], const uint32_t a[4], const uint32_t b[2]) {
    asm volatile(
        "mma.sync.aligned.m16n8k16.row.col.f32.bf16.bf16.f32 "
        "{%0,%1,%2,%3}, {%4,%5,%6,%7}, {%8,%9}, {%0,%1,%2,%3};"
        : "+f"(d[0]), "+f"(d[1]), "+f"(d[2]), "+f"(d[3])
        : "r"(a[0]), "r"(a[1]), "r"(a[2]), "r"(a[3]), "r"(b[0]), "r"(b[1]));
}

__device__ __forceinline__ __nv_bfloat162 u2b(uint32_t u) {
    return *reinterpret_cast<__nv_bfloat162*>(&u);
}
__device__ __forceinline__ uint32_t b2u(__nv_bfloat162 v) {
    return *reinterpret_cast<uint32_t*>(&v);
}
__device__ __forceinline__ float ex2(float v) {
    float r; asm("ex2.approx.f32 %0, %1;" : "=f"(r) : "f"(v)); return r;
}

// -(L1 over 16 bf16 components held as 8 bf16x2 regs); exact lo/hi extraction.
__device__ __forceinline__ float l1_neg(const uint32_t* mj, const uint32_t* mi) {
    __nv_bfloat162 d0 = __habs2(__hsub2(u2b(mj[0]), u2b(mi[0])));
    __nv_bfloat162 d1 = __habs2(__hsub2(u2b(mj[1]), u2b(mi[1])));
    __nv_bfloat162 d2 = __habs2(__hsub2(u2b(mj[2]), u2b(mi[2])));
    __nv_bfloat162 d3 = __habs2(__hsub2(u2b(mj[3]), u2b(mi[3])));
    __nv_bfloat162 d4 = __habs2(__hsub2(u2b(mj[4]), u2b(mi[4])));
    __nv_bfloat162 d5 = __habs2(__hsub2(u2b(mj[5]), u2b(mi[5])));
    __nv_bfloat162 d6 = __habs2(__hsub2(u2b(mj[6]), u2b(mi[6])));
    __nv_bfloat162 d7 = __habs2(__hsub2(u2b(mj[7]), u2b(mi[7])));
    __nv_bfloat162 s = __hadd2(__hadd2(__hadd2(d0, d1), __hadd2(d2, d3)),
                               __hadd2(__hadd2(d4, d5), __hadd2(d6, d7)));
    uint32_t u = b2u(s);
    float lo = __uint_as_float(u << 16);          // bf16 -> f32 zero-extension: exact
    float hi = __uint_as_float(u & 0xFFFF0000u);
    return (-lo) - hi;                            // FADD with neg modifiers
}

// ---------------------------------------------------------------------------
// Fused prep: blocks [0,256): copy x -> out, convert x -> g_xb (bf16),
//             blocks [0,128) also init out[:,1024:] = -1.
//             blocks [256,1280): transpose+scale W -> g_Wb (bf16).
// ---------------------------------------------------------------------------
__global__ __launch_bounds__(256)
void prep_kernel(const float* __restrict__ x, const float* __restrict__ W,
                 float* __restrict__ out) {
    if (blockIdx.x < 256) {
        int t = blockIdx.x * 256 + threadIdx.x;     // handles 8 floats
        int row  = t >> 7;
        int col8 = (t & 127) * 8;
        const float4* src = reinterpret_cast<const float4*>(x + (size_t)row * AA + col8);
        float4 a = src[0], b = src[1];
        // copy to out
        float4* dst = reinterpret_cast<float4*>(out + (size_t)row * OUTW + col8);
        dst[0] = a; dst[1] = b;
        // convert to bf16
        __nv_bfloat162 p0 = __float22bfloat162_rn(make_float2(a.x, a.y));
        __nv_bfloat162 p1 = __float22bfloat162_rn(make_float2(a.z, a.w));
        __nv_bfloat162 p2 = __float22bfloat162_rn(make_float2(b.x, b.y));
        __nv_bfloat162 p3 = __float22bfloat162_rn(make_float2(b.z, b.w));
        uint4 o; o.x = b2u(p0); o.y = b2u(p1); o.z = b2u(p2); o.w = b2u(p3);
        reinterpret_cast<uint4*>(g_xb)[t] = o;
        // init output tail to -1 (cancels the j==i term later)
        if (blockIdx.x < 128) {
            int idx = blockIdx.x * 256 + threadIdx.x;   // 0..32767
            int i = idx >> 6;
            int b2 = idx & 63;
            out[(size_t)i * OUTW + AA + b2] = -1.0f;
        }
    } else {
        __shared__ float tile[32][33];
        int idx = blockIdx.x - 256;                 // 0..1023
        const int n0 = (idx & 31) * 32;
        const int k0 = (idx >> 5) * 32;
        const int tx = threadIdx.x & 31;
        const int ty = threadIdx.x >> 5;            // 0..7
#pragma unroll
        for (int r = 0; r < 4; r++)
            tile[ty + 8 * r][tx] = W[(size_t)(k0 + ty + 8 * r) * AA + n0 + tx];
        __syncthreads();
#pragma unroll
        for (int r = 0; r < 4; r++) {
            int n = n0 + ty + 8 * r;
            g_Wb[(size_t)n * AA + k0 + tx] =
                __float2bfloat16(tile[tx][ty + 8 * r] * LOG2E);
        }
    }
}

// ---------------------------------------------------------------------------
// GEMM via mma.sync bf16 m16n8k16. Block 64x64, 128 threads (4 warps 2x2),
// K chunked by 64, swizzled smem, register prefetch. Epilogue -> bf16 g_Mb.
// ---------------------------------------------------------------------------
#define BK 64
#define NCH (AA / BK)   // 16

__global__ __launch_bounds__(128)
void gemm_mma_kernel() {
    __shared__ __align__(1024) __nv_bfloat16 sA[64 * BK];   // 8 KB
    __shared__ __align__(1024) __nv_bfloat16 sB[64 * BK];   // 8 KB

    const int tid = threadIdx.x;
    const int wid = tid >> 5;
    const int l   = tid & 31;
    const int mw  = wid & 1;
    const int nw  = wid >> 1;
    const int row0 = blockIdx.y * 64;
    const int col0 = blockIdx.x * 64;

    const uint32_t sA_addr = smem_u32(sA);
    const uint32_t sB_addr = smem_u32(sB);

    float acc[2][4][4];
#pragma unroll
    for (int mt = 0; mt < 2; mt++)
#pragma unroll
        for (int nt = 0; nt < 4; nt++)
#pragma unroll
            for (int e = 0; e < 4; e++) acc[mt][nt][e] = 0.0f;

    uint4 pa[4], pb[4];
#pragma unroll
    for (int s = 0; s < 4; s++) {
        int ch = tid + s * 128;
        int r = ch >> 3, u = ch & 7;
        pa[s] = *reinterpret_cast<const uint4*>(g_xb + (size_t)(row0 + r) * AA + u * 8);
        pb[s] = *reinterpret_cast<const uint4*>(g_Wb + (size_t)(col0 + r) * AA + u * 8);
    }

    const int aRow0 = ((l >> 3) & 1) * 8 + (l & 7) + mw * 32;
    const int bRow0 = nw * 32 + ((l >> 4) << 3) + (l & 7);
    const int aKsel = (l >> 4);
    const int bKsel = ((l >> 3) & 1);
    const int swz   = (l & 7);

    for (int c = 0; c < NCH; c++) {
#pragma unroll
        for (int s = 0; s < 4; s++) {
            int ch = tid + s * 128;
            int r = ch >> 3, u = ch & 7;
            uint32_t off = (uint32_t)(r * 128 + ((u ^ (r & 7)) << 4));
            *reinterpret_cast<uint4*>(reinterpret_cast<char*>(sA) + off) = pa[s];
            *reinterpret_cast<uint4*>(reinterpret_cast<char*>(sB) + off) = pb[s];
        }
        __syncthreads();

        if (c + 1 < NCH) {
            int k0 = (c + 1) * BK;
#pragma unroll
            for (int s = 0; s < 4; s++) {
                int ch = tid + s * 128;
                int r = ch >> 3, u = ch & 7;
                pa[s] = *reinterpret_cast<const uint4*>(g_xb + (size_t)(row0 + r) * AA + k0 + u * 8);
                pb[s] = *reinterpret_cast<const uint4*>(g_Wb + (size_t)(col0 + r) * AA + k0 + u * 8);
            }
        }

#pragma unroll
        for (int ks = 0; ks < 4; ks++) {
            uint32_t af[2][4], bf[4][2];
#pragma unroll
            for (int mt = 0; mt < 2; mt++) {
                int row = aRow0 + mt * 16;
                uint32_t u = (uint32_t)(ks * 2 + aKsel);
                uint32_t addr = sA_addr + (uint32_t)(row * 128) + (((u ^ swz)) << 4);
                LDMATRIX_X4(af[mt][0], af[mt][1], af[mt][2], af[mt][3], addr);
            }
#pragma unroll
            for (int ng = 0; ng < 2; ng++) {
                int row = bRow0 + ng * 16;
                uint32_t u = (uint32_t)(ks * 2 + bKsel);
                uint32_t addr = sB_addr + (uint32_t)(row * 128) + (((u ^ swz)) << 4);
                uint32_t r0, r1, r2, r3;
                LDMATRIX_X4(r0, r1, r2, r3, addr);
                bf[ng * 2 + 0][0] = r0; bf[ng * 2 + 0][1] = r1;
                bf[ng * 2 + 1][0] = r2; bf[ng * 2 + 1][1] = r3;
            }
#pragma unroll
            for (int mt = 0; mt < 2; mt++)
#pragma unroll
                for (int nt = 0; nt < 4; nt++)
                    mma_bf16(acc[mt][nt], af[mt], bf[nt]);
        }
        __syncthreads();
    }

    // Epilogue: bf16x2 into pairwise layout g_Mb[row*512 + b*8 + c2]
    const int g = l >> 2;
    const int cc2 = (l & 3) * 2;
#pragma unroll
    for (int mt = 0; mt < 2; mt++) {
#pragma unroll
        for (int nt = 0; nt < 4; nt++) {
            int gcol = col0 + nw * 32 + nt * 8 + cc2;
            int b  = gcol >> 4;
            int c2 = (gcol & 15) >> 1;
            int rowA = row0 + mw * 32 + mt * 16 + g;
            __nv_bfloat162 v0 = __float22bfloat162_rn(
                make_float2(acc[mt][nt][0], acc[mt][nt][1]));
            __nv_bfloat162 v1 = __float22bfloat162_rn(
                make_float2(acc[mt][nt][2], acc[mt][nt][3]));
            g_Mb[(size_t)rowA * 512 + b * 8 + c2]       = b2u(v0);
            g_Mb[(size_t)(rowA + 8) * 512 + b * 8 + c2] = b2u(v1);
        }
    }
}

// ---------------------------------------------------------------------------
// Pairwise, triangular tiles over 16 groups of 32 rows. 136 blocks x 512 thr
// (single co-resident wave). Thread (b = t&63, isp = t>>6 in 0..7): owns
// 4 i-rows, loops 32 j-rows (prefetch depth 2). Results atomically added
// straight into out[:,1024:] (pre-initialized to -1 by prep).
// ---------------------------------------------------------------------------
__global__ __launch_bounds__(512)
void pairwise_kernel(float* __restrict__ out) {
    const int t   = threadIdx.x;
    const int b   = t & 63;
    const int isp = t >> 6;        // 0..7

    // decode triangular tile: offset(g) = g*(33-g)/2 for NGRP=16
    int tt = blockIdx.x;
    int gi = 0;
#pragma unroll
    for (int g = 1; g < NGRP; g++)
        if ((g * (2 * NGRP + 1 - g)) / 2 <= tt) gi = g;
    int gj = gi + (tt - (gi * (2 * NGRP + 1 - gi)) / 2);

    const int i0 = gi * GSZ + isp * 4;
    const int j0 = gj * GSZ;

    __shared__ float red[16][8][BB];   // 32 KB (half of the j-group at a time)

    const uint4* Mb4 = reinterpret_cast<const uint4*>(g_Mb);

    // load 4 i-rows (8 u32 each)
    uint32_t mi[4][8];
#pragma unroll
    for (int k = 0; k < 4; k++) {
        uint4 v0 = Mb4[(size_t)(i0 + k) * 128 + b * 2];
        uint4 v1 = Mb4[(size_t)(i0 + k) * 128 + b * 2 + 1];
        mi[k][0] = v0.x; mi[k][1] = v0.y; mi[k][2] = v0.z; mi[k][3] = v0.w;
        mi[k][4] = v1.x; mi[k][5] = v1.y; mi[k][6] = v1.z; mi[k][7] = v1.w;
    }

    float acc_i[4] = {0.f, 0.f, 0.f, 0.f};

    // prefetch depth 2 on j-rows
    uint32_t jb[2][8];
#pragma unroll
    for (int p = 0; p < 2; p++) {
        uint4 v0 = Mb4[(size_t)(j0 + p) * 128 + b * 2];
        uint4 v1 = Mb4[(size_t)(j0 + p) * 128 + b * 2 + 1];
        jb[p][0] = v0.x; jb[p][1] = v0.y; jb[p][2] = v0.z; jb[p][3] = v0.w;
        jb[p][4] = v1.x; jb[p][5] = v1.y; jb[p][6] = v1.z; jb[p][7] = v1.w;
    }

    for (int half = 0; half < 2; half++) {
#pragma unroll
        for (int jj = 0; jj < 16; jj++) {
            const int jg = half * 16 + jj;
            uint32_t mj[8];
#pragma unroll
            for (int c = 0; c < 8; c++) mj[c] = jb[jg & 1][c];
            if (jg + 2 < GSZ) {
                uint4 v0 = Mb4[(size_t)(j0 + jg + 2) * 128 + b * 2];
                uint4 v1 = Mb4[(size_t)(j0 + jg + 2) * 128 + b * 2 + 1];
                jb[jg & 1][0] = v0.x; jb[jg & 1][1] = v0.y;
                jb[jg & 1][2] = v0.z; jb[jg & 1][3] = v0.w;
                jb[jg & 1][4] = v1.x; jb[jg & 1][5] = v1.y;
                jb[jg & 1][6] = v1.z; jb[jg & 1][7] = v1.w;
            }

            float e0 = ex2(l1_neg(mj, mi[0]));
            float e1 = ex2(l1_neg(mj, mi[1]));
            float e2 = ex2(l1_neg(mj, mi[2]));
            float e3 = ex2(l1_neg(mj, mi[3]));
            acc_i[0] += e0; acc_i[1] += e1; acc_i[2] += e2; acc_i[3] += e3;
            red[jj][isp][b] = (e0 + e1) + (e2 + e3);
        }
        __syncthreads();
        // j-side flush for this half (off-diagonal tiles only)
        if (gi != gj) {
#pragma unroll
            for (int w = 0; w < 2; w++) {
                int cell = t + w * 512;           // 0..1023
                int jj = cell >> 6;
                int bb = cell & 63;
                float s = red[jj][0][bb] + red[jj][1][bb] + red[jj][2][bb] + red[jj][3][bb]
                        + red[jj][4][bb] + red[jj][5][bb] + red[jj][6][bb] + red[jj][7][bb];
                atomicAdd(out + (size_t)(j0 + half * 16 + jj) * OUTW + AA + bb, s);
            }
        }
        __syncthreads();
    }

    // i-side: atomic add per owned row
#pragma unroll
    for (int k = 0; k < 4; k++)
        atomicAdd(out + (size_t)(i0 + k) * OUTW + AA + b, acc_i[k]);
}

// ---------------------------------------------------------------------------
extern "C" void kernel_launch(void* const* d_in, const int* in_sizes, int n_in,
                              void* d_out, int out_size) {
    const float* x = (const float*)d_in[0];   // (512, 1024)
    const float* T = (const float*)d_in[1];   // (1024, 1024)
    float* out = (float*)d_out;               // (512, 1088)

    prep_kernel<<<1280, 256>>>(x, T, out);

    dim3 ggrid(AA / 64, NN / 64);             // (16, 8) = 128 blocks
    gemm_mma_kernel<<<ggrid, 128>>>();

    pairwise_kernel<<<NTILES, 512>>>(out);    // 136 blocks, single wave
}

// round 10
// speedup vs baseline: 1.0683x; 1.0077x over previous
#include <cuda_runtime.h>
#include <cuda_bf16.h>
#include <cstdint>

// Problem constants: N=512, A=1024, B=64, C=16
#define NN   512
#define AA   1024
#define BB   64
#define CC   16
#define OUTW (AA + BB)   // 1088

#define NGRP   16            // row groups of 32
#define GSZ    32
#define NTILES (NGRP * (NGRP + 1) / 2)   // 136

#define LOG2E 1.44269504088896340736f

// ---------------- device scratch ----------------
// M (pre-scaled by log2e) in bf16x2: g_Mb[row*512 + b*8 + c2]
__device__ uint32_t g_Mb[NN * 512];
__device__ __nv_bfloat16 g_xb[NN * AA];     // x in bf16
__device__ __nv_bfloat16 g_Wb[AA * AA];     // W * log2e in bf16, native [k][n]

// ---------------- helpers ----------------
__device__ __forceinline__ uint32_t smem_u32(const void* p) {
    uint32_t a;
    asm("{ .reg .u64 t; cvta.to.shared.u64 t, %1; cvt.u32.u64 %0, t; }" : "=r"(a) : "l"(p));
    return a;
}
#define LDMATRIX_X4(r0, r1, r2, r3, addr) \
    asm volatile("ldmatrix.sync.aligned.m8n8.x4.shared.b16 {%0,%1,%2,%3}, [%4];" \
        : "=r"(r0), "=r"(r1), "=r"(r2), "=r"(r3) : "r"(addr))
#define LDMATRIX_X4_T(r0, r1, r2, r3, addr) \
    asm volatile("ldmatrix.sync.aligned.m8n8.x4.trans.shared.b16 {%0,%1,%2,%3}, [%4];" \
        : "=r"(r0), "=r"(r1), "=r"(r2), "=r"(r3) : "r"(addr))

__device__ __forceinline__ void mma_bf16(float d[4], const uint32_t a[4], const uint32_t b[2]) {
    asm volatile(
        "mma.sync.aligned.m16n8k16.row.col.f32.bf16.bf16.f32 "
        "{%0,%1,%2,%3}, {%4,%5,%6,%7}, {%8,%9}, {%0,%1,%2,%3};"
        : "+f"(d[0]), "+f"(d[1]), "+f"(d[2]), "+f"(d[3])
        : "r"(a[0]), "r"(a[1]), "r"(a[2]), "r"(a[3]), "r"(b[0]), "r"(b[1]));
}

__device__ __forceinline__ __nv_bfloat162 u2b(uint32_t u) {
    return *reinterpret_cast<__nv_bfloat162*>(&u);
}
__device__ __forceinline__ uint32_t b2u(__nv_bfloat162 v) {
    return *reinterpret_cast<uint32_t*>(&v);
}
__device__ __forceinline__ float ex2(float v) {
    float r; asm("ex2.approx.f32 %0, %1;" : "=f"(r) : "f"(v)); return r;
}

// -(L1 over 16 bf16 components held as 8 bf16x2 regs); exact lo/hi extraction.
__device__ __forceinline__ float l1_neg(const uint32_t* mj, const uint32_t* mi) {
    __nv_bfloat162 d0 = __habs2(__hsub2(u2b(mj[0]), u2b(mi[0])));
    __nv_bfloat162 d1 = __habs2(__hsub2(u2b(mj[1]), u2b(mi[1])));
    __nv_bfloat162 d2 = __habs2(__hsub2(u2b(mj[2]), u2b(mi[2])));
    __nv_bfloat162 d3 = __habs2(__hsub2(u2b(mj[3]), u2b(mi[3])));
    __nv_bfloat162 d4 = __habs2(__hsub2(u2b(mj[4]), u2b(mi[4])));
    __nv_bfloat162 d5 = __habs2(__hsub2(u2b(mj[5]), u2b(mi[5])));
    __nv_bfloat162 d6 = __habs2(__hsub2(u2b(mj[6]), u2b(mi[6])));
    __nv_bfloat162 d7 = __habs2(__hsub2(u2b(mj[7]), u2b(mi[7])));
    __nv_bfloat162 s = __hadd2(__hadd2(__hadd2(d0, d1), __hadd2(d2, d3)),
                               __hadd2(__hadd2(d4, d5), __hadd2(d6, d7)));
    uint32_t u = b2u(s);
    float lo = __uint_as_float(u << 16);          // bf16 -> f32 zero-extension: exact
    float hi = __uint_as_float(u & 0xFFFF0000u);
    return (-lo) - hi;                            // FADD with neg modifiers
}

// ---------------------------------------------------------------------------
// Fused prep (pure streaming, no smem):
//   blocks [0,256):   copy x -> out, convert x -> g_xb; first 128 also
//                     init out[:,1024:] = -1.
//   blocks [256,768): elementwise W * log2e -> g_Wb (bf16, [k][n]).
// ---------------------------------------------------------------------------
__global__ __launch_bounds__(256)
void prep_kernel(const float* __restrict__ x, const float* __restrict__ W,
                 float* __restrict__ out) {
    if (blockIdx.x < 256) {
        int t = blockIdx.x * 256 + threadIdx.x;     // handles 8 floats
        int row  = t >> 7;
        int col8 = (t & 127) * 8;
        const float4* src = reinterpret_cast<const float4*>(x + (size_t)row * AA + col8);
        float4 a = src[0], b = src[1];
        float4* dst = reinterpret_cast<float4*>(out + (size_t)row * OUTW + col8);
        dst[0] = a; dst[1] = b;
        __nv_bfloat162 p0 = __float22bfloat162_rn(make_float2(a.x, a.y));
        __nv_bfloat162 p1 = __float22bfloat162_rn(make_float2(a.z, a.w));
        __nv_bfloat162 p2 = __float22bfloat162_rn(make_float2(b.x, b.y));
        __nv_bfloat162 p3 = __float22bfloat162_rn(make_float2(b.z, b.w));
        uint4 o; o.x = b2u(p0); o.y = b2u(p1); o.z = b2u(p2); o.w = b2u(p3);
        reinterpret_cast<uint4*>(g_xb)[t] = o;
        if (blockIdx.x < 128) {
            int idx = blockIdx.x * 256 + threadIdx.x;   // 0..32767
            int i = idx >> 6;
            int b2 = idx & 63;
            out[(size_t)i * OUTW + AA + b2] = -1.0f;
        }
    } else {
        int t = (blockIdx.x - 256) * 256 + threadIdx.x; // handles 8 floats
        const float4* src = reinterpret_cast<const float4*>(W) + 2 * (size_t)t;
        float4 a = src[0], b = src[1];
        __nv_bfloat162 p0 = __float22bfloat162_rn(make_float2(a.x * LOG2E, a.y * LOG2E));
        __nv_bfloat162 p1 = __float22bfloat162_rn(make_float2(a.z * LOG2E, a.w * LOG2E));
        __nv_bfloat162 p2 = __float22bfloat162_rn(make_float2(b.x * LOG2E, b.y * LOG2E));
        __nv_bfloat162 p3 = __float22bfloat162_rn(make_float2(b.z * LOG2E, b.w * LOG2E));
        uint4 o; o.x = b2u(p0); o.y = b2u(p1); o.z = b2u(p2); o.w = b2u(p3);
        reinterpret_cast<uint4*>(g_Wb)[t] = o;
    }
}

// ---------------------------------------------------------------------------
// GEMM via mma.sync bf16 m16n8k16. Block 64x64, 128 threads (4 warps 2x2),
// K chunked by 64, swizzled smem, register prefetch.
// A: row-major [m][k]; B: native [k][n], fragments via ldmatrix.x4.trans.
// Epilogue -> bf16 g_Mb.
// ---------------------------------------------------------------------------
#define BK 64
#define NCH (AA / BK)   // 16

__global__ __launch_bounds__(128)
void gemm_mma_kernel() {
    __shared__ __align__(1024) __nv_bfloat16 sA[64 * BK];   // 8 KB  [m-row][k]
    __shared__ __align__(1024) __nv_bfloat16 sB[64 * BK];   // 8 KB  [k-row][n]

    const int tid = threadIdx.x;
    const int wid = tid >> 5;
    const int l   = tid & 31;
    const int mw  = wid & 1;
    const int nw  = wid >> 1;
    const int row0 = blockIdx.y * 64;
    const int col0 = blockIdx.x * 64;

    const uint32_t sA_addr = smem_u32(sA);
    const uint32_t sB_addr = smem_u32(sB);

    float acc[2][4][4];
#pragma unroll
    for (int mt = 0; mt < 2; mt++)
#pragma unroll
        for (int nt = 0; nt < 4; nt++)
#pragma unroll
            for (int e = 0; e < 4; e++) acc[mt][nt][e] = 0.0f;

    uint4 pa[4], pb[4];
#pragma unroll
    for (int s = 0; s < 4; s++) {
        int ch = tid + s * 128;
        int r = ch >> 3, u = ch & 7;
        pa[s] = *reinterpret_cast<const uint4*>(g_xb + (size_t)(row0 + r) * AA + u * 8);
        pb[s] = *reinterpret_cast<const uint4*>(g_Wb + (size_t)r * AA + col0 + u * 8);
    }

    const int aRow0 = ((l >> 3) & 1) * 8 + (l & 7) + mw * 32;
    const int aKsel = (l >> 4);
    const int bRowL = ((l >> 3) & 1) * 8 + (l & 7);   // k-row within 16-step
    const int bUsel = (l >> 4);                        // n 16B-unit selector
    const int swz   = (l & 7);

    for (int c = 0; c < NCH; c++) {
#pragma unroll
        for (int s = 0; s < 4; s++) {
            int ch = tid + s * 128;
            int r = ch >> 3, u = ch & 7;
            uint32_t off = (uint32_t)(r * 128 + ((u ^ (r & 7)) << 4));
            *reinterpret_cast<uint4*>(reinterpret_cast<char*>(sA) + off) = pa[s];
            *reinterpret_cast<uint4*>(reinterpret_cast<char*>(sB) + off) = pb[s];
        }
        __syncthreads();

        if (c + 1 < NCH) {
            int k0 = (c + 1) * BK;
#pragma unroll
            for (int s = 0; s < 4; s++) {
                int ch = tid + s * 128;
                int r = ch >> 3, u = ch & 7;
                pa[s] = *reinterpret_cast<const uint4*>(g_xb + (size_t)(row0 + r) * AA + k0 + u * 8);
                pb[s] = *reinterpret_cast<const uint4*>(g_Wb + (size_t)(k0 + r) * AA + col0 + u * 8);
            }
        }

#pragma unroll
        for (int ks = 0; ks < 4; ks++) {
            uint32_t af[2][4], bf[4][2];
#pragma unroll
            for (int mt = 0; mt < 2; mt++) {
                int row = aRow0 + mt * 16;
                uint32_t u = (uint32_t)(ks * 2 + aKsel);
                uint32_t addr = sA_addr + (uint32_t)(row * 128) + (((u ^ swz)) << 4);
                LDMATRIX_X4(af[mt][0], af[mt][1], af[mt][2], af[mt][3], addr);
            }
            // B fragments from [k][n] tile via trans ldmatrix:
            // lanes 0-7: rows ks*16+0..7 @ n-unit base; 8-15: rows +8..15;
            // 16-23/24-31: same rows @ n-unit base+1.
#pragma unroll
            for (int h = 0; h < 2; h++) {
                int row = ks * 16 + bRowL;
                uint32_t u = (uint32_t)(nw * 4 + h * 2 + bUsel);
                uint32_t addr = sB_addr + (uint32_t)(row * 128) + (((u ^ (row & 7))) << 4);
                uint32_t r0, r1, r2, r3;
                LDMATRIX_X4_T(r0, r1, r2, r3, addr);
                bf[h * 2 + 0][0] = r0; bf[h * 2 + 0][1] = r1;
                bf[h * 2 + 1][0] = r2; bf[h * 2 + 1][1] = r3;
            }
#pragma unroll
            for (int mt = 0; mt < 2; mt++)
#pragma unroll
                for (int nt = 0; nt < 4; nt++)
                    mma_bf16(acc[mt][nt], af[mt], bf[nt]);
        }
        __syncthreads();
    }

    // Epilogue: bf16x2 into pairwise layout g_Mb[row*512 + b*8 + c2]
    const int g = l >> 2;
    const int cc2 = (l & 3) * 2;
#pragma unroll
    for (int mt = 0; mt < 2; mt++) {
#pragma unroll
        for (int nt = 0; nt < 4; nt++) {
            int gcol = col0 + nw * 32 + nt * 8 + cc2;
            int b  = gcol >> 4;
            int c2 = (gcol & 15) >> 1;
            int rowA = row0 + mw * 32 + mt * 16 + g;
            __nv_bfloat162 v0 = __float22bfloat162_rn(
                make_float2(acc[mt][nt][0], acc[mt][nt][1]));
            __nv_bfloat162 v1 = __float22bfloat162_rn(
                make_float2(acc[mt][nt][2], acc[mt][nt][3]));
            g_Mb[(size_t)rowA * 512 + b * 8 + c2]       = b2u(v0);
            g_Mb[(size_t)(rowA + 8) * 512 + b * 8 + c2] = b2u(v1);
        }
    }
}

// ---------------------------------------------------------------------------
// Pairwise, triangular tiles over 16 groups of 32 rows. 136 blocks x 512 thr
// (single co-resident wave). Thread (b = t&63, isp = t>>6 in 0..7): owns
// 4 i-rows, loops 32 j-rows (prefetch depth 2). Results atomically added
// straight into out[:,1024:] (pre-initialized to -1 by prep).
// ---------------------------------------------------------------------------
__global__ __launch_bounds__(512)
void pairwise_kernel(float* __restrict__ out) {
    const int t   = threadIdx.x;
    const int b   = t & 63;
    const int isp = t >> 6;        // 0..7

    // decode triangular tile: offset(g) = g*(33-g)/2 for NGRP=16
    int tt = blockIdx.x;
    int gi = 0;
#pragma unroll
    for (int g = 1; g < NGRP; g++)
        if ((g * (2 * NGRP + 1 - g)) / 2 <= tt) gi = g;
    int gj = gi + (tt - (gi * (2 * NGRP + 1 - gi)) / 2);

    const int i0 = gi * GSZ + isp * 4;
    const int j0 = gj * GSZ;

    __shared__ float red[16][8][BB];   // 32 KB (half of the j-group at a time)

    const uint4* Mb4 = reinterpret_cast<const uint4*>(g_Mb);

    // load 4 i-rows (8 u32 each)
    uint32_t mi[4][8];
#pragma unroll
    for (int k = 0; k < 4; k++) {
        uint4 v0 = Mb4[(size_t)(i0 + k) * 128 + b * 2];
        uint4 v1 = Mb4[(size_t)(i0 + k) * 128 + b * 2 + 1];
        mi[k][0] = v0.x; mi[k][1] = v0.y; mi[k][2] = v0.z; mi[k][3] = v0.w;
        mi[k][4] = v1.x; mi[k][5] = v1.y; mi[k][6] = v1.z; mi[k][7] = v1.w;
    }

    float acc_i[4] = {0.f, 0.f, 0.f, 0.f};

    // prefetch depth 2 on j-rows
    uint32_t jb[2][8];
#pragma unroll
    for (int p = 0; p < 2; p++) {
        uint4 v0 = Mb4[(size_t)(j0 + p) * 128 + b * 2];
        uint4 v1 = Mb4[(size_t)(j0 + p) * 128 + b * 2 + 1];
        jb[p][0] = v0.x; jb[p][1] = v0.y; jb[p][2] = v0.z; jb[p][3] = v0.w;
        jb[p][4] = v1.x; jb[p][5] = v1.y; jb[p][6] = v1.z; jb[p][7] = v1.w;
    }

    for (int half = 0; half < 2; half++) {
#pragma unroll
        for (int jj = 0; jj < 16; jj++) {
            const int jg = half * 16 + jj;
            uint32_t mj[8];
#pragma unroll
            for (int c = 0; c < 8; c++) mj[c] = jb[jg & 1][c];
            if (jg + 2 < GSZ) {
                uint4 v0 = Mb4[(size_t)(j0 + jg + 2) * 128 + b * 2];
                uint4 v1 = Mb4[(size_t)(j0 + jg + 2) * 128 + b * 2 + 1];
                jb[jg & 1][0] = v0.x; jb[jg & 1][1] = v0.y;
                jb[jg & 1][2] = v0.z; jb[jg & 1][3] = v0.w;
                jb[jg & 1][4] = v1.x; jb[jg & 1][5] = v1.y;
                jb[jg & 1][6] = v1.z; jb[jg & 1][7] = v1.w;
            }

            float e0 = ex2(l1_neg(mj, mi[0]));
            float e1 = ex2(l1_neg(mj, mi[1]));
            float e2 = ex2(l1_neg(mj, mi[2]));
            float e3 = ex2(l1_neg(mj, mi[3]));
            acc_i[0] += e0; acc_i[1] += e1; acc_i[2] += e2; acc_i[3] += e3;
            red[jj][isp][b] = (e0 + e1) + (e2 + e3);
        }
        __syncthreads();
        // j-side flush for this half (off-diagonal tiles only)
        if (gi != gj) {
#pragma unroll
            for (int w = 0; w < 2; w++) {
                int cell = t + w * 512;           // 0..1023
                int jj = cell >> 6;
                int bb = cell & 63;
                float s = red[jj][0][bb] + red[jj][1][bb] + red[jj][2][bb] + red[jj][3][bb]
                        + red[jj][4][bb] + red[jj][5][bb] + red[jj][6][bb] + red[jj][7][bb];
                atomicAdd(out + (size_t)(j0 + half * 16 + jj) * OUTW + AA + bb, s);
            }
        }
        __syncthreads();
    }

    // i-side: atomic add per owned row
#pragma unroll
    for (int k = 0; k < 4; k++)
        atomicAdd(out + (size_t)(i0 + k) * OUTW + AA + b, acc_i[k]);
}

// ---------------------------------------------------------------------------
extern "C" void kernel_launch(void* const* d_in, const int* in_sizes, int n_in,
                              void* d_out, int out_size) {
    const float* x = (const float*)d_in[0];   // (512, 1024)
    const float* T = (const float*)d_in[1];   // (1024, 1024)
    float* out = (float*)d_out;               // (512, 1088)

    prep_kernel<<<768, 256>>>(x, T, out);

    dim3 ggrid(AA / 64, NN / 64);             // (16, 8) = 128 blocks
    gemm_mma_kernel<<<ggrid, 128>>>();

    pairwise_kernel<<<NTILES, 512>>>(out);    // 136 blocks, single wave
}